// round 1
// baseline (speedup 1.0000x reference)
#include <cuda_runtime.h>
#include <math.h>

#define BB 4
#define LL 2048
#define IN_DIM 64
#define DM 256
#define DI 512
#define DS 16
#define DCONV 4
#define DTR 16
#define NLAYERS 4
#define BL (BB*LL)   // 8192 rows

// ---------------- scratch (static __device__, no allocation) ----------------
__device__ float g_h[BL*DM];        // residual stream
__device__ float g_xz[BL*2*DI];     // in-layer projection (u | z)
__device__ float g_u[BL*DI];        // conv+silu output
__device__ float g_dbc[BL*48];      // dt(16) | B(16) | C(16)
__device__ float g_delta[BL*DI];    // softplus(dt @ dtw + dtb)
__device__ float g_y[BL*DI];        // scan output * silu(z)
__device__ float g_ln[BL*DM];       // pre-layernorm (gemm_out + residual)

// ---------------- generic GEMM: C[M,N] = A[M,K](lda) @ W[N,K]^T --------------
// epilogue: optional bias[N], optional act (1 = softplus), optional res[M,N] add
#define BM 64
#define BN 64
#define BK 16

__global__ void gemm_kernel(const float* __restrict__ A, int lda,
                            const float* __restrict__ W,
                            const float* __restrict__ bias,
                            const float* __restrict__ res,
                            float* __restrict__ C,
                            int M, int N, int K, int act)
{
    __shared__ float sA[BK][BM+4];
    __shared__ float sB[BK][BN+4];
    int tid = threadIdx.x;
    int tx = tid & 15;        // N direction (16 groups of 4)
    int ty = tid >> 4;        // M direction (16 groups of 4)
    int bm = blockIdx.y * BM;
    int bn = blockIdx.x * BN;

    float acc[4][4];
    #pragma unroll
    for (int i = 0; i < 4; i++)
        #pragma unroll
        for (int j = 0; j < 4; j++) acc[i][j] = 0.f;

    for (int k0 = 0; k0 < K; k0 += BK) {
        // A tile 64x16 -> sA[k][m]
        #pragma unroll
        for (int j = 0; j < 4; j++) {
            int e = tid + j*256;
            int r = e >> 4, c = e & 15;
            sA[c][r] = A[(size_t)(bm + r)*lda + k0 + c];
        }
        // W tile: rows are N, cols are K -> sB[k][n]
        #pragma unroll
        for (int j = 0; j < 4; j++) {
            int e = tid + j*256;
            int n = e >> 4, c = e & 15;
            int gn = bn + n;
            sB[c][n] = (gn < N) ? W[(size_t)gn*K + k0 + c] : 0.f;
        }
        __syncthreads();
        #pragma unroll
        for (int kk = 0; kk < BK; kk++) {
            float a[4], b[4];
            #pragma unroll
            for (int i = 0; i < 4; i++) a[i] = sA[kk][ty*4 + i];
            #pragma unroll
            for (int i = 0; i < 4; i++) b[i] = sB[kk][tx*4 + i];
            #pragma unroll
            for (int i = 0; i < 4; i++)
                #pragma unroll
                for (int j = 0; j < 4; j++)
                    acc[i][j] = fmaf(a[i], b[j], acc[i][j]);
        }
        __syncthreads();
    }

    #pragma unroll
    for (int i = 0; i < 4; i++) {
        int gm = bm + ty*4 + i;
        #pragma unroll
        for (int j = 0; j < 4; j++) {
            int gn = bn + tx*4 + j;
            if (gn < N) {
                float v = acc[i][j];
                if (bias) v += bias[gn];
                if (act == 1) v = (v > 15.f) ? v : log1pf(__expf(v));  // softplus
                if (res)  v += res[(size_t)gm*N + gn];
                C[(size_t)gm*N + gn] = v;
            }
        }
    }
}

// ---------------- depthwise causal conv (width 4) + SiLU --------------------
__global__ void conv_silu_kernel(const float* __restrict__ xz,
                                 const float* __restrict__ convw,
                                 const float* __restrict__ convb,
                                 float* __restrict__ u)
{
    int idx = blockIdx.x * blockDim.x + threadIdx.x;   // over BL*DI
    if (idx >= BL*DI) return;
    int d  = idx & (DI-1);
    int bt = idx >> 9;          // DI = 512
    int t  = bt & (LL-1);

    float acc = convb[d];
    #pragma unroll
    for (int k = 0; k < DCONV; k++) {
        int tt = t - (DCONV-1) + k;
        if (tt >= 0)
            acc = fmaf(xz[(size_t)(bt - (DCONV-1) + k)*(2*DI) + d],
                       convw[d*DCONV + k], acc);
    }
    float sig = 1.f / (1.f + __expf(-acc));
    u[idx] = acc * sig;
}

// ---------------- selective scan: thread per (b, d, s) ----------------------
// 16 lanes form one (b,d) group; shfl-xor reduce over states for y_t.
__global__ void scan_kernel(const float* __restrict__ xz,
                            const float* __restrict__ u_arr,
                            const float* __restrict__ dbc,
                            const float* __restrict__ delta_arr,
                            const float* __restrict__ a_log,
                            const float* __restrict__ dparam,
                            float* __restrict__ y_arr)
{
    int gid  = blockIdx.x * blockDim.x + threadIdx.x;
    int s    = gid & 15;
    int pair = gid >> 4;           // 0 .. B*DI-1
    int d    = pair & (DI-1);
    int b    = pair >> 9;

    float A  = -__expf(a_log[d*DS + s]);
    float Dp = dparam[d];
    float h  = 0.f;
    int base = b * LL;

    #pragma unroll 4
    for (int t = 0; t < LL; t++) {
        int row = base + t;
        float delta = delta_arr[(size_t)row*DI + d];
        float uu    = u_arr[(size_t)row*DI + d];
        float Bt    = dbc[(size_t)row*48 + DTR + s];
        float Ct    = dbc[(size_t)row*48 + DTR + DS + s];

        float dA = __expf(delta * A);
        h = fmaf(dA, h, delta * uu * Bt);

        float p = h * Ct;
        p += __shfl_xor_sync(0xffffffffu, p, 8);
        p += __shfl_xor_sync(0xffffffffu, p, 4);
        p += __shfl_xor_sync(0xffffffffu, p, 2);
        p += __shfl_xor_sync(0xffffffffu, p, 1);

        if (s == 0) {
            float z = xz[(size_t)row*(2*DI) + DI + d];
            float sig = 1.f / (1.f + __expf(-z));
            y_arr[(size_t)row*DI + d] = (p + uu * Dp) * (z * sig);
        }
    }
}

// ---------------- layernorm over 256 features (one warp per row) ------------
__global__ void ln_kernel(const float* __restrict__ x,
                          const float* __restrict__ w,
                          const float* __restrict__ b,
                          float* __restrict__ out)
{
    int warp = (blockIdx.x * blockDim.x + threadIdx.x) >> 5;
    int lane = threadIdx.x & 31;
    if (warp >= BL) return;
    const float* row = x + (size_t)warp*DM;

    float v[8];
    float sum = 0.f, sq = 0.f;
    #pragma unroll
    for (int k = 0; k < 8; k++) {
        v[k] = row[lane + k*32];
        sum += v[k];
        sq = fmaf(v[k], v[k], sq);
    }
    #pragma unroll
    for (int o = 16; o; o >>= 1) {
        sum += __shfl_xor_sync(0xffffffffu, sum, o);
        sq  += __shfl_xor_sync(0xffffffffu, sq,  o);
    }
    float mu  = sum * (1.f/DM);
    float var = sq * (1.f/DM) - mu*mu;
    float inv = rsqrtf(var + 1e-5f);
    #pragma unroll
    for (int k = 0; k < 8; k++) {
        int c = lane + k*32;
        out[(size_t)warp*DM + c] = (v[k]-mu)*inv*w[c] + b[c];
    }
}

// ---------------- host orchestration ----------------------------------------
extern "C" void kernel_launch(void* const* d_in, const int* in_sizes, int n_in,
                              void* d_out, int out_size)
{
    const float* x          = (const float*)d_in[0];
    const float* in_proj_w  = (const float*)d_in[1];
    const float* in_proj_b  = (const float*)d_in[2];
    const float* out_proj_w = (const float*)d_in[3];
    const float* out_proj_b = (const float*)d_in[4];
    const float* inw        = (const float*)d_in[5];
    const float* convw      = (const float*)d_in[6];
    const float* convb      = (const float*)d_in[7];
    const float* xpw        = (const float*)d_in[8];
    const float* dtw        = (const float*)d_in[9];
    const float* dtb        = (const float*)d_in[10];
    const float* a_log      = (const float*)d_in[11];
    const float* dparam     = (const float*)d_in[12];
    const float* outw       = (const float*)d_in[13];
    const float* lnw        = (const float*)d_in[14];
    const float* lnb        = (const float*)d_in[15];
    float* out = (float*)d_out;

    float *h, *xz, *u, *dbc, *delta, *y, *ln;
    cudaGetSymbolAddress((void**)&h,     g_h);
    cudaGetSymbolAddress((void**)&xz,    g_xz);
    cudaGetSymbolAddress((void**)&u,     g_u);
    cudaGetSymbolAddress((void**)&dbc,   g_dbc);
    cudaGetSymbolAddress((void**)&delta, g_delta);
    cudaGetSymbolAddress((void**)&y,     g_y);
    cudaGetSymbolAddress((void**)&ln,    g_ln);

    const int MB = BL/BM;   // 128

    // h = x @ in_proj_w^T + in_proj_b
    gemm_kernel<<<dim3(DM/BN, MB), 256>>>(x, IN_DIM, in_proj_w, in_proj_b,
                                          nullptr, h, BL, DM, IN_DIM, 0);

    for (int l = 0; l < NLAYERS; l++) {
        // xz = h @ inw[l]^T
        gemm_kernel<<<dim3((2*DI)/BN, MB), 256>>>(h, DM, inw + (size_t)l*2*DI*DM,
                                                  nullptr, nullptr, xz, BL, 2*DI, DM, 0);
        // u = silu(causal_conv(xz[:, :DI]))
        conv_silu_kernel<<<(BL*DI)/256, 256>>>(xz, convw + l*DI*DCONV,
                                               convb + l*DI, u);
        // dbc = u @ xpw[l]^T   (N=48, one tile col with guards)
        gemm_kernel<<<dim3(1, MB), 256>>>(u, DI, xpw + (size_t)l*48*DI,
                                          nullptr, nullptr, dbc, BL, 48, DI, 0);
        // delta = softplus(dt @ dtw[l]^T + dtb[l])
        gemm_kernel<<<dim3(DI/BN, MB), 256>>>(dbc, 48, dtw + (size_t)l*DI*DTR,
                                              dtb + l*DI, nullptr, delta, BL, DI, DTR, 1);
        // selective scan + gating
        scan_kernel<<<(BB*DI*DS)/256, 256>>>(xz, u, dbc, delta,
                                             a_log + (size_t)l*DI*DS,
                                             dparam + l*DI, y);
        // ln_in = y @ outw[l]^T + residual(h)
        gemm_kernel<<<dim3(DM/BN, MB), 256>>>(y, DI, outw + (size_t)l*DM*DI,
                                              nullptr, h, ln, BL, DM, DI, 0);
        // h = layernorm(ln_in)
        ln_kernel<<<BL/8, 256>>>(ln, lnw + l*DM, lnb + l*DM, h);
    }

    // out = h @ out_proj_w^T + out_proj_b
    gemm_kernel<<<dim3(DM/BN, MB), 256>>>(h, DM, out_proj_w, out_proj_b,
                                          nullptr, out, BL, DM, DM, 0);
}

// round 2
// speedup vs baseline: 1.1771x; 1.1771x over previous
#include <cuda_runtime.h>
#include <math.h>

#define BB 4
#define LL 2048
#define IN_DIM 64
#define DM 256
#define DI 512
#define DS 16
#define DCONV 4
#define DTR 16
#define NLAYERS 4
#define BL (BB*LL)   // 8192 rows

// ---------------- scratch (static __device__, no allocation) ----------------
__device__ float g_h[BL*DM];        // residual stream
__device__ float g_xz[BL*2*DI];     // in-layer projection (u | z)
__device__ float g_u[BL*DI];        // conv+silu output
__device__ float g_dbc[BL*48];      // dt(16) | B(16) | C(16)
__device__ float g_delta[BL*DI];    // softplus(dt @ dtw + dtb)
__device__ float g_y[BL*DI];        // scan output * silu(z)
__device__ float g_ln[BL*DM];       // pre-layernorm (gemm_out + residual)

// ---------------- GEMM: C[M,N] = A[M,K](lda) @ W[N,K]^T ---------------------
// 128x64 block tile, BK=16, 256 threads, 8x4 per-thread accumulators.
// epilogue: optional bias[N], optional act (1 = softplus), optional res add.
#define BM 128
#define BN 64
#define BK 16

__global__ __launch_bounds__(256) void gemm_kernel(
    const float* __restrict__ A, int lda,
    const float* __restrict__ W,
    const float* __restrict__ bias,
    const float* __restrict__ res,
    float* __restrict__ C,
    int M, int N, int K, int act)
{
    __shared__ float sA[BK][BM+4];   // k-major, 16 x 132
    __shared__ float sB[BK][BN+4];   // k-major, 16 x 68

    int tid = threadIdx.x;
    int tx = tid & 15;        // N direction: 16 groups x 4 cols
    int ty = tid >> 4;        // M direction: 16 groups x 8 rows
    int bm = blockIdx.y * BM;
    int bn = blockIdx.x * BN;

    float acc[8][4];
    #pragma unroll
    for (int i = 0; i < 8; i++)
        #pragma unroll
        for (int j = 0; j < 4; j++) acc[i][j] = 0.f;

    for (int k0 = 0; k0 < K; k0 += BK) {
        // A tile: 128 rows x 16 k-cols = 512 float4, 2 per thread
        #pragma unroll
        for (int j = 0; j < 2; j++) {
            int e = tid + j*256;
            int r = e >> 2;
            int c4 = (e & 3) * 4;
            float4 v = *(const float4*)(A + (size_t)(bm + r)*lda + k0 + c4);
            sA[c4+0][r] = v.x; sA[c4+1][r] = v.y;
            sA[c4+2][r] = v.z; sA[c4+3][r] = v.w;
        }
        // W tile: 64 N-rows x 16 k-cols = 256 float4, 1 per thread
        {
            int r = tid >> 2;
            int c4 = (tid & 3) * 4;
            int gn = bn + r;
            float4 v = make_float4(0.f, 0.f, 0.f, 0.f);
            if (gn < N) v = *(const float4*)(W + (size_t)gn*K + k0 + c4);
            sB[c4+0][r] = v.x; sB[c4+1][r] = v.y;
            sB[c4+2][r] = v.z; sB[c4+3][r] = v.w;
        }
        __syncthreads();

        #pragma unroll
        for (int kk = 0; kk < BK; kk++) {
            float a[8], b[4];
            *(float4*)&a[0] = *(const float4*)&sA[kk][ty*8];
            *(float4*)&a[4] = *(const float4*)&sA[kk][ty*8 + 4];
            *(float4*)&b[0] = *(const float4*)&sB[kk][tx*4];
            #pragma unroll
            for (int i = 0; i < 8; i++)
                #pragma unroll
                for (int j = 0; j < 4; j++)
                    acc[i][j] = fmaf(a[i], b[j], acc[i][j]);
        }
        __syncthreads();
    }

    // epilogue: rows bm+ty*8..+7, cols bn+tx*4..+3 (contiguous, N%4==0 always)
    int gn0 = bn + tx*4;
    if (gn0 < N) {
        float4 bv = make_float4(0.f, 0.f, 0.f, 0.f);
        if (bias) bv = *(const float4*)(bias + gn0);
        #pragma unroll
        for (int i = 0; i < 8; i++) {
            int gm = bm + ty*8 + i;
            float4 v = make_float4(acc[i][0], acc[i][1], acc[i][2], acc[i][3]);
            v.x += bv.x; v.y += bv.y; v.z += bv.z; v.w += bv.w;
            if (act == 1) {   // softplus
                v.x = (v.x > 15.f) ? v.x : log1pf(__expf(v.x));
                v.y = (v.y > 15.f) ? v.y : log1pf(__expf(v.y));
                v.z = (v.z > 15.f) ? v.z : log1pf(__expf(v.z));
                v.w = (v.w > 15.f) ? v.w : log1pf(__expf(v.w));
            }
            if (res) {
                float4 rv = *(const float4*)(res + (size_t)gm*N + gn0);
                v.x += rv.x; v.y += rv.y; v.z += rv.z; v.w += rv.w;
            }
            *(float4*)(C + (size_t)gm*N + gn0) = v;
        }
    }
}

// ---------------- depthwise causal conv (width 4) + SiLU --------------------
__global__ void conv_silu_kernel(const float* __restrict__ xz,
                                 const float* __restrict__ convw,
                                 const float* __restrict__ convb,
                                 float* __restrict__ u)
{
    int idx = blockIdx.x * blockDim.x + threadIdx.x;   // over BL*DI
    if (idx >= BL*DI) return;
    int d  = idx & (DI-1);
    int bt = idx >> 9;          // DI = 512
    int t  = bt & (LL-1);

    float acc = convb[d];
    #pragma unroll
    for (int k = 0; k < DCONV; k++) {
        int tt = t - (DCONV-1) + k;
        if (tt >= 0)
            acc = fmaf(xz[(size_t)(bt - (DCONV-1) + k)*(2*DI) + d],
                       convw[d*DCONV + k], acc);
    }
    float sig = 1.f / (1.f + __expf(-acc));
    u[idx] = acc * sig;
}

// ---------------- selective scan: thread per (b, d, s) ----------------------
__global__ void scan_kernel(const float* __restrict__ xz,
                            const float* __restrict__ u_arr,
                            const float* __restrict__ dbc,
                            const float* __restrict__ delta_arr,
                            const float* __restrict__ a_log,
                            const float* __restrict__ dparam,
                            float* __restrict__ y_arr)
{
    int gid  = blockIdx.x * blockDim.x + threadIdx.x;
    int s    = gid & 15;
    int pair = gid >> 4;           // 0 .. B*DI-1
    int d    = pair & (DI-1);
    int b    = pair >> 9;

    float A  = -__expf(a_log[d*DS + s]);
    float Dp = dparam[d];
    float h  = 0.f;
    int base = b * LL;

    #pragma unroll 4
    for (int t = 0; t < LL; t++) {
        int row = base + t;
        float delta = delta_arr[(size_t)row*DI + d];
        float uu    = u_arr[(size_t)row*DI + d];
        float Bt    = dbc[(size_t)row*48 + DTR + s];
        float Ct    = dbc[(size_t)row*48 + DTR + DS + s];

        float dA = __expf(delta * A);
        h = fmaf(dA, h, delta * uu * Bt);

        float p = h * Ct;
        p += __shfl_xor_sync(0xffffffffu, p, 8);
        p += __shfl_xor_sync(0xffffffffu, p, 4);
        p += __shfl_xor_sync(0xffffffffu, p, 2);
        p += __shfl_xor_sync(0xffffffffu, p, 1);

        if (s == 0) {
            float z = xz[(size_t)row*(2*DI) + DI + d];
            float sig = 1.f / (1.f + __expf(-z));
            y_arr[(size_t)row*DI + d] = (p + uu * Dp) * (z * sig);
        }
    }
}

// ---------------- layernorm over 256 features (one warp per row) ------------
__global__ void ln_kernel(const float* __restrict__ x,
                          const float* __restrict__ w,
                          const float* __restrict__ b,
                          float* __restrict__ out)
{
    int warp = (blockIdx.x * blockDim.x + threadIdx.x) >> 5;
    int lane = threadIdx.x & 31;
    if (warp >= BL) return;
    const float* row = x + (size_t)warp*DM;

    float v[8];
    float sum = 0.f, sq = 0.f;
    #pragma unroll
    for (int k = 0; k < 8; k++) {
        v[k] = row[lane + k*32];
        sum += v[k];
        sq = fmaf(v[k], v[k], sq);
    }
    #pragma unroll
    for (int o = 16; o; o >>= 1) {
        sum += __shfl_xor_sync(0xffffffffu, sum, o);
        sq  += __shfl_xor_sync(0xffffffffu, sq,  o);
    }
    float mu  = sum * (1.f/DM);
    float var = sq * (1.f/DM) - mu*mu;
    float inv = rsqrtf(var + 1e-5f);
    #pragma unroll
    for (int k = 0; k < 8; k++) {
        int c = lane + k*32;
        out[(size_t)warp*DM + c] = (v[k]-mu)*inv*w[c] + b[c];
    }
}

// ---------------- host orchestration ----------------------------------------
extern "C" void kernel_launch(void* const* d_in, const int* in_sizes, int n_in,
                              void* d_out, int out_size)
{
    const float* x          = (const float*)d_in[0];
    const float* in_proj_w  = (const float*)d_in[1];
    const float* in_proj_b  = (const float*)d_in[2];
    const float* out_proj_w = (const float*)d_in[3];
    const float* out_proj_b = (const float*)d_in[4];
    const float* inw        = (const float*)d_in[5];
    const float* convw      = (const float*)d_in[6];
    const float* convb      = (const float*)d_in[7];
    const float* xpw        = (const float*)d_in[8];
    const float* dtw        = (const float*)d_in[9];
    const float* dtb        = (const float*)d_in[10];
    const float* a_log      = (const float*)d_in[11];
    const float* dparam     = (const float*)d_in[12];
    const float* outw       = (const float*)d_in[13];
    const float* lnw        = (const float*)d_in[14];
    const float* lnb        = (const float*)d_in[15];
    float* out = (float*)d_out;

    float *h, *xz, *u, *dbc, *delta, *y, *ln;
    cudaGetSymbolAddress((void**)&h,     g_h);
    cudaGetSymbolAddress((void**)&xz,    g_xz);
    cudaGetSymbolAddress((void**)&u,     g_u);
    cudaGetSymbolAddress((void**)&dbc,   g_dbc);
    cudaGetSymbolAddress((void**)&delta, g_delta);
    cudaGetSymbolAddress((void**)&y,     g_y);
    cudaGetSymbolAddress((void**)&ln,    g_ln);

    const int MB = BL/BM;   // 64

    // h = x @ in_proj_w^T + in_proj_b
    gemm_kernel<<<dim3(DM/BN, MB), 256>>>(x, IN_DIM, in_proj_w, in_proj_b,
                                          nullptr, h, BL, DM, IN_DIM, 0);

    for (int l = 0; l < NLAYERS; l++) {
        // xz = h @ inw[l]^T
        gemm_kernel<<<dim3((2*DI)/BN, MB), 256>>>(h, DM, inw + (size_t)l*2*DI*DM,
                                                  nullptr, nullptr, xz, BL, 2*DI, DM, 0);
        // u = silu(causal_conv(xz[:, :DI]))
        conv_silu_kernel<<<(BL*DI)/256, 256>>>(xz, convw + l*DI*DCONV,
                                               convb + l*DI, u);
        // dbc = u @ xpw[l]^T   (N=48, one tile col with guards)
        gemm_kernel<<<dim3(1, MB), 256>>>(u, DI, xpw + (size_t)l*48*DI,
                                          nullptr, nullptr, dbc, BL, 48, DI, 0);
        // delta = softplus(dt @ dtw[l]^T + dtb[l])
        gemm_kernel<<<dim3(DI/BN, MB), 256>>>(dbc, 48, dtw + (size_t)l*DI*DTR,
                                              dtb + l*DI, nullptr, delta, BL, DI, DTR, 1);
        // selective scan + gating
        scan_kernel<<<(BB*DI*DS)/256, 256>>>(xz, u, dbc, delta,
                                             a_log + (size_t)l*DI*DS,
                                             dparam + l*DI, y);
        // ln_in = y @ outw[l]^T + residual(h)
        gemm_kernel<<<dim3(DM/BN, MB), 256>>>(y, DI, outw + (size_t)l*DM*DI,
                                              nullptr, h, ln, BL, DM, DI, 0);
        // h = layernorm(ln_in)
        ln_kernel<<<BL/8, 256>>>(ln, lnw + l*DM, lnb + l*DM, h);
    }

    // out = h @ out_proj_w^T + out_proj_b
    gemm_kernel<<<dim3(DM/BN, MB), 256>>>(h, DM, out_proj_w, out_proj_b,
                                          nullptr, out, BL, DM, DM, 0);
}

// round 4
// speedup vs baseline: 1.1811x; 1.0034x over previous
#include <cuda_runtime.h>
#include <math.h>
#include <stdint.h>

#define BB 4
#define LL 2048
#define IN_DIM 64
#define DM 256
#define DI 512
#define DS 16
#define DCONV 4
#define DTR 16
#define NLAYERS 4
#define BL (BB*LL)   // 8192 rows

// ---------------- scratch (static __device__, no allocation) ----------------
__device__ float g_h[BL*DM];
__device__ float g_xz[BL*2*DI];
__device__ float g_u[BL*DI];
__device__ float g_dbc[BL*48];
__device__ float g_delta[BL*DI];
__device__ float g_y[BL*DI];
__device__ float g_ln[BL*DM];

// ---------------- helpers ----------------------------------------------------
__device__ __forceinline__ uint32_t f2tf32(float x) {
    uint32_t u;
    asm("cvt.rna.tf32.f32 %0, %1;" : "=r"(u) : "f"(x));
    return u;
}
__device__ __forceinline__ void mma16n8k8(float* d, const uint32_t* a, const uint32_t* b) {
    asm volatile(
        "mma.sync.aligned.m16n8k8.row.col.f32.tf32.tf32.f32 "
        "{%0,%1,%2,%3}, {%4,%5,%6,%7}, {%8,%9}, {%0,%1,%2,%3};"
        : "+f"(d[0]), "+f"(d[1]), "+f"(d[2]), "+f"(d[3])
        : "r"(a[0]), "r"(a[1]), "r"(a[2]), "r"(a[3]), "r"(b[0]), "r"(b[1]));
}

// ================== split-tf32 tensor-core GEMM: C = A @ W^T =================
// Block: 256 threads (8 warps, 4x2), tile 128(M) x 64(N) x 16(K).
// Per warp: 32x32, as 2(m16) x 4(n8) mma tiles, 2 k-steps of 8 per BK.
// Split: D += Ah*Bh + Al*Bh + Ah*Bl (three mma per tile per k-step).
// smem stride 20 words -> conflict-free fragment loads.
#define ASTRIDE 20
#define BSTRIDE 20

__global__ __launch_bounds__(256) void mma_gemm(
    const float* __restrict__ A, int lda,
    const float* __restrict__ W,
    const float* __restrict__ bias,
    const float* __restrict__ res,
    float* __restrict__ C,
    int N, int K, int act)
{
    __shared__ uint32_t sAh[128*ASTRIDE];
    __shared__ uint32_t sAl[128*ASTRIDE];
    __shared__ uint32_t sBh[64*BSTRIDE];
    __shared__ uint32_t sBl[64*BSTRIDE];

    int tid = threadIdx.x;
    int wid = tid >> 5, lid = tid & 31;
    int warp_m = wid >> 1;          // 0..3
    int warp_n = wid & 1;           // 0..1
    int bm = blockIdx.y * 128;
    int bn = blockIdx.x * 64;

    float acc[2][4][4];
    #pragma unroll
    for (int i = 0; i < 2; i++)
        #pragma unroll
        for (int j = 0; j < 4; j++)
            #pragma unroll
            for (int e = 0; e < 4; e++) acc[i][j][e] = 0.f;

    for (int k0 = 0; k0 < K; k0 += 16) {
        // ---- fill A tile: 128 rows x 16 k (512 float4, 2/thread) ----
        #pragma unroll
        for (int j = 0; j < 2; j++) {
            int e = tid + j*256;
            int r = e >> 2;
            int c4 = (e & 3) * 4;
            float4 v = *(const float4*)(A + (size_t)(bm + r)*lda + k0 + c4);
            uint4 hi = make_uint4(f2tf32(v.x), f2tf32(v.y), f2tf32(v.z), f2tf32(v.w));
            uint4 lo = make_uint4(f2tf32(v.x - __uint_as_float(hi.x)),
                                  f2tf32(v.y - __uint_as_float(hi.y)),
                                  f2tf32(v.z - __uint_as_float(hi.z)),
                                  f2tf32(v.w - __uint_as_float(hi.w)));
            *(uint4*)&sAh[r*ASTRIDE + c4] = hi;
            *(uint4*)&sAl[r*ASTRIDE + c4] = lo;
        }
        // ---- fill B tile: 64 N-rows x 16 k (256 float4, 1/thread) ----
        {
            int r = tid >> 2;
            int c4 = (tid & 3) * 4;
            int gn = bn + r;
            float4 v = make_float4(0.f, 0.f, 0.f, 0.f);
            if (gn < N) v = *(const float4*)(W + (size_t)gn*K + k0 + c4);
            uint4 hi = make_uint4(f2tf32(v.x), f2tf32(v.y), f2tf32(v.z), f2tf32(v.w));
            uint4 lo = make_uint4(f2tf32(v.x - __uint_as_float(hi.x)),
                                  f2tf32(v.y - __uint_as_float(hi.y)),
                                  f2tf32(v.z - __uint_as_float(hi.z)),
                                  f2tf32(v.w - __uint_as_float(hi.w)));
            *(uint4*)&sBh[r*BSTRIDE + c4] = hi;
            *(uint4*)&sBl[r*BSTRIDE + c4] = lo;
        }
        __syncthreads();

        #pragma unroll
        for (int ks = 0; ks < 2; ks++) {
            int kk = ks * 8;
            // A fragments (2 m16 tiles), hi and lo
            uint32_t ah[2][4], al[2][4];
            {
                int r0 = warp_m*32 + (lid >> 2);
                int c0 = kk + (lid & 3);
                #pragma unroll
                for (int im = 0; im < 2; im++) {
                    int base = (r0 + im*16)*ASTRIDE + c0;
                    ah[im][0] = sAh[base];
                    ah[im][1] = sAh[base + 8*ASTRIDE];
                    ah[im][2] = sAh[base + 4];
                    ah[im][3] = sAh[base + 8*ASTRIDE + 4];
                    al[im][0] = sAl[base];
                    al[im][1] = sAl[base + 8*ASTRIDE];
                    al[im][2] = sAl[base + 4];
                    al[im][3] = sAl[base + 8*ASTRIDE + 4];
                }
            }
            // B fragments (4 n8 tiles), hi and lo
            uint32_t bh[4][2], bl[4][2];
            {
                int n0 = warp_n*32 + (lid >> 2);
                int c0 = kk + (lid & 3);
                #pragma unroll
                for (int jn = 0; jn < 4; jn++) {
                    int base = (n0 + jn*8)*BSTRIDE + c0;
                    bh[jn][0] = sBh[base];
                    bh[jn][1] = sBh[base + 4];
                    bl[jn][0] = sBl[base];
                    bl[jn][1] = sBl[base + 4];
                }
            }
            #pragma unroll
            for (int im = 0; im < 2; im++)
                #pragma unroll
                for (int jn = 0; jn < 4; jn++) {
                    mma16n8k8(acc[im][jn], ah[im], bh[jn]);
                    mma16n8k8(acc[im][jn], al[im], bh[jn]);
                    mma16n8k8(acc[im][jn], ah[im], bl[jn]);
                }
        }
        __syncthreads();
    }

    // ---- epilogue ----
    // c0,c1 -> (row, 2*(lane&3) + {0,1}); c2,c3 -> row+8
    int gm0 = bm + warp_m*32 + (lid >> 2);
    int gnb = bn + warp_n*32 + 2*(lid & 3);
    #pragma unroll
    for (int im = 0; im < 2; im++) {
        #pragma unroll
        for (int jn = 0; jn < 4; jn++) {
            int gn = gnb + jn*8;
            if (gn < N) {
                float b0 = 0.f, b1 = 0.f;
                if (bias) { b0 = bias[gn]; b1 = bias[gn+1]; }
                #pragma unroll
                for (int half = 0; half < 2; half++) {
                    int gm = gm0 + im*16 + half*8;
                    float v0 = acc[im][jn][half*2+0] + b0;
                    float v1 = acc[im][jn][half*2+1] + b1;
                    if (act == 1) {   // softplus
                        v0 = (v0 > 15.f) ? v0 : log1pf(__expf(v0));
                        v1 = (v1 > 15.f) ? v1 : log1pf(__expf(v1));
                    }
                    if (res) {
                        float2 rv = *(const float2*)(res + (size_t)gm*N + gn);
                        v0 += rv.x; v1 += rv.y;
                    }
                    *(float2*)(C + (size_t)gm*N + gn) = make_float2(v0, v1);
                }
            }
        }
    }
}

// ---------------- depthwise causal conv (width 4) + SiLU --------------------
__global__ void conv_silu_kernel(const float* __restrict__ xz,
                                 const float* __restrict__ convw,
                                 const float* __restrict__ convb,
                                 float* __restrict__ u)
{
    int idx = blockIdx.x * blockDim.x + threadIdx.x;
    if (idx >= BL*DI) return;
    int d  = idx & (DI-1);
    int bt = idx >> 9;
    int t  = bt & (LL-1);

    float acc = convb[d];
    #pragma unroll
    for (int k = 0; k < DCONV; k++) {
        int tt = t - (DCONV-1) + k;
        if (tt >= 0)
            acc = fmaf(xz[(size_t)(bt - (DCONV-1) + k)*(2*DI) + d],
                       convw[d*DCONV + k], acc);
    }
    float sig = 1.f / (1.f + __expf(-acc));
    u[idx] = acc * sig;
}

// ---------------- selective scan: thread per (b, d, s) ----------------------
__global__ void scan_kernel(const float* __restrict__ xz,
                            const float* __restrict__ u_arr,
                            const float* __restrict__ dbc,
                            const float* __restrict__ delta_arr,
                            const float* __restrict__ a_log,
                            const float* __restrict__ dparam,
                            float* __restrict__ y_arr)
{
    int gid  = blockIdx.x * blockDim.x + threadIdx.x;
    int s    = gid & 15;
    int pair = gid >> 4;
    int d    = pair & (DI-1);
    int b    = pair >> 9;

    float A  = -__expf(a_log[d*DS + s]);
    float Dp = dparam[d];
    float h  = 0.f;
    int base = b * LL;

    #pragma unroll 4
    for (int t = 0; t < LL; t++) {
        int row = base + t;
        float delta = delta_arr[(size_t)row*DI + d];
        float uu    = u_arr[(size_t)row*DI + d];
        float Bt    = dbc[(size_t)row*48 + DTR + s];
        float Ct    = dbc[(size_t)row*48 + DTR + DS + s];

        float dA = __expf(delta * A);
        h = fmaf(dA, h, delta * uu * Bt);

        float p = h * Ct;
        p += __shfl_xor_sync(0xffffffffu, p, 8);
        p += __shfl_xor_sync(0xffffffffu, p, 4);
        p += __shfl_xor_sync(0xffffffffu, p, 2);
        p += __shfl_xor_sync(0xffffffffu, p, 1);

        if (s == 0) {
            float z = xz[(size_t)row*(2*DI) + DI + d];
            float sig = 1.f / (1.f + __expf(-z));
            y_arr[(size_t)row*DI + d] = (p + uu * Dp) * (z * sig);
        }
    }
}

// ---------------- layernorm over 256 features (one warp per row) ------------
__global__ void ln_kernel(const float* __restrict__ x,
                          const float* __restrict__ w,
                          const float* __restrict__ b,
                          float* __restrict__ out)
{
    int warp = (blockIdx.x * blockDim.x + threadIdx.x) >> 5;
    int lane = threadIdx.x & 31;
    if (warp >= BL) return;
    const float* row = x + (size_t)warp*DM;

    float v[8];
    float sum = 0.f, sq = 0.f;
    #pragma unroll
    for (int k = 0; k < 8; k++) {
        v[k] = row[lane + k*32];
        sum += v[k];
        sq = fmaf(v[k], v[k], sq);
    }
    #pragma unroll
    for (int o = 16; o; o >>= 1) {
        sum += __shfl_xor_sync(0xffffffffu, sum, o);
        sq  += __shfl_xor_sync(0xffffffffu, sq,  o);
    }
    float mu  = sum * (1.f/DM);
    float var = sq * (1.f/DM) - mu*mu;
    float inv = rsqrtf(var + 1e-5f);
    #pragma unroll
    for (int k = 0; k < 8; k++) {
        int c = lane + k*32;
        out[(size_t)warp*DM + c] = (v[k]-mu)*inv*w[c] + b[c];
    }
}

// ---------------- host orchestration ----------------------------------------
static inline void launch_gemm(const float* A, int lda, const float* W,
                               const float* bias, const float* res,
                               float* C, int N, int K, int act)
{
    dim3 grid((N + 63) / 64, BL / 128);
    mma_gemm<<<grid, 256>>>(A, lda, W, bias, res, C, N, K, act);
}

extern "C" void kernel_launch(void* const* d_in, const int* in_sizes, int n_in,
                              void* d_out, int out_size)
{
    const float* x          = (const float*)d_in[0];
    const float* in_proj_w  = (const float*)d_in[1];
    const float* in_proj_b  = (const float*)d_in[2];
    const float* out_proj_w = (const float*)d_in[3];
    const float* out_proj_b = (const float*)d_in[4];
    const float* inw        = (const float*)d_in[5];
    const float* convw      = (const float*)d_in[6];
    const float* convb      = (const float*)d_in[7];
    const float* xpw        = (const float*)d_in[8];
    const float* dtw        = (const float*)d_in[9];
    const float* dtb        = (const float*)d_in[10];
    const float* a_log      = (const float*)d_in[11];
    const float* dparam     = (const float*)d_in[12];
    const float* outw       = (const float*)d_in[13];
    const float* lnw        = (const float*)d_in[14];
    const float* lnb        = (const float*)d_in[15];
    float* out = (float*)d_out;

    float *h, *xz, *u, *dbc, *delta, *y, *ln;
    cudaGetSymbolAddress((void**)&h,     g_h);
    cudaGetSymbolAddress((void**)&xz,    g_xz);
    cudaGetSymbolAddress((void**)&u,     g_u);
    cudaGetSymbolAddress((void**)&dbc,   g_dbc);
    cudaGetSymbolAddress((void**)&delta, g_delta);
    cudaGetSymbolAddress((void**)&y,     g_y);
    cudaGetSymbolAddress((void**)&ln,    g_ln);

    // h = x @ in_proj_w^T + in_proj_b
    launch_gemm(x, IN_DIM, in_proj_w, in_proj_b, nullptr, h, DM, IN_DIM, 0);

    for (int l = 0; l < NLAYERS; l++) {
        // xz = h @ inw[l]^T
        launch_gemm(h, DM, inw + (size_t)l*2*DI*DM, nullptr, nullptr, xz, 2*DI, DM, 0);
        // u = silu(causal_conv(xz[:, :DI]))
        conv_silu_kernel<<<(BL*DI)/256, 256>>>(xz, convw + l*DI*DCONV, convb + l*DI, u);
        // dbc = u @ xpw[l]^T   (N=48 with guards)
        launch_gemm(u, DI, xpw + (size_t)l*48*DI, nullptr, nullptr, dbc, 48, DI, 0);
        // delta = softplus(dt @ dtw[l]^T + dtb[l])   (A = dbc, lda=48, K=16)
        launch_gemm(dbc, 48, dtw + (size_t)l*DI*DTR, dtb + l*DI, nullptr, delta, DI, DTR, 1);
        // selective scan + gating
        scan_kernel<<<(BB*DI*DS)/256, 256>>>(xz, u, dbc, delta,
                                             a_log + (size_t)l*DI*DS, dparam + l*DI, y);
        // ln_in = y @ outw[l]^T + residual(h)
        launch_gemm(y, DI, outw + (size_t)l*DM*DI, nullptr, h, ln, DM, DI, 0);
        // h = layernorm(ln_in)
        ln_kernel<<<BL/8, 256>>>(ln, lnw + l*DM, lnb + l*DM, h);
    }

    // out = h @ out_proj_w^T + out_proj_b
    launch_gemm(h, DM, out_proj_w, out_proj_b, nullptr, out, DM, DM, 0);
}

// round 5
// speedup vs baseline: 4.0782x; 3.4528x over previous
#include <cuda_runtime.h>
#include <math.h>
#include <stdint.h>

#define BB 4
#define LL 2048
#define IN_DIM 64
#define DM 256
#define DI 512
#define DS 16
#define DCONV 4
#define DTR 16
#define NLAYERS 4
#define BL (BB*LL)   // 8192 rows

// ---------------- scratch (static __device__, no allocation) ----------------
__device__ float g_h[BL*DM];
__device__ float g_xz[BL*2*DI];
__device__ float g_u[BL*DI];
__device__ float g_dbc[BL*48];
__device__ float g_delta[BL*DI];
__device__ float g_y[BL*DI];
__device__ float g_ln[BL*DM];

// ---------------- helpers ----------------------------------------------------
__device__ __forceinline__ uint32_t smem_u32(const void* p) {
    uint32_t a;
    asm("{ .reg .u64 t; cvta.to.shared.u64 t, %1; cvt.u32.u64 %0, t; }"
        : "=r"(a) : "l"(p));
    return a;
}
__device__ __forceinline__ uint32_t f2tf32(float x) {
    uint32_t u;
    asm("cvt.rna.tf32.f32 %0, %1;" : "=r"(u) : "f"(x));
    return u;
}
__device__ __forceinline__ void mma16n8k8(float* d, const uint32_t* a, const uint32_t* b) {
    asm volatile(
        "mma.sync.aligned.m16n8k8.row.col.f32.tf32.tf32.f32 "
        "{%0,%1,%2,%3}, {%4,%5,%6,%7}, {%8,%9}, {%0,%1,%2,%3};"
        : "+f"(d[0]), "+f"(d[1]), "+f"(d[2]), "+f"(d[3])
        : "r"(a[0]), "r"(a[1]), "r"(a[2]), "r"(a[3]), "r"(b[0]), "r"(b[1]));
}
__device__ __forceinline__ void cp16(uint32_t dst, const float* src, int srcsize) {
    asm volatile("cp.async.ca.shared.global [%0], [%1], 16, %2;"
                 :: "r"(dst), "l"(src), "r"(srcsize) : "memory");
}
#define CP_COMMIT()  asm volatile("cp.async.commit_group;" ::: "memory")
#define CP_WAIT(n)   asm volatile("cp.async.wait_group %0;" :: "n"(n) : "memory")

// ================== split-tf32 tensor-core GEMM: C = A @ W^T =================
// Block: 256 threads (8 warps, 4x2), tile 128(M) x 64(N) x 16(K).
// cp.async double-buffered raw-float smem; tf32 hi/lo split in registers.
#define TSTR 20   // smem row stride in words (conflict-free, 16B-aligned rows)

__global__ __launch_bounds__(256) void mma_gemm(
    const float* __restrict__ A, int lda,
    const float* __restrict__ W,
    const float* __restrict__ bias,
    const float* __restrict__ res,
    float* __restrict__ C,
    int N, int K, int act)
{
    __shared__ float sA[2][128*TSTR];
    __shared__ float sB[2][64*TSTR];

    int tid = threadIdx.x;
    int wid = tid >> 5, lid = tid & 31;
    int warp_m = wid >> 1;          // 0..3
    int warp_n = wid & 1;           // 0..1
    int bm = blockIdx.y * 128;
    int bn = blockIdx.x * 64;

    uint32_t aBase = smem_u32(&sA[0][0]);
    uint32_t bBase = smem_u32(&sB[0][0]);
    const uint32_t A_STAGE = 128*TSTR*4;
    const uint32_t B_STAGE = 64*TSTR*4;

    // per-thread load coords
    int ar0 = tid >> 2;              // A: 2 rows (ar0, ar0+64), col group
    int ac4 = (tid & 3) * 4;
    int br  = tid >> 2;              // B: 1 row
    int bc4 = (tid & 3) * 4;
    int bgn = bn + br;
    int bpred = (bgn < N) ? 16 : 0;
    const float* bsrc_row = W + (size_t)(bgn < N ? bgn : 0) * K;

    float acc[2][4][4];
    #pragma unroll
    for (int i = 0; i < 2; i++)
        #pragma unroll
        for (int j = 0; j < 4; j++)
            #pragma unroll
            for (int e = 0; e < 4; e++) acc[i][j][e] = 0.f;

    int nk = K >> 4;

    // prefetch stage 0
    {
        cp16(aBase + (uint32_t)((ar0*TSTR + ac4)*4),
             A + (size_t)(bm + ar0)*lda + ac4, 16);
        cp16(aBase + (uint32_t)(((ar0+64)*TSTR + ac4)*4),
             A + (size_t)(bm + ar0 + 64)*lda + ac4, 16);
        cp16(bBase + (uint32_t)((br*TSTR + bc4)*4), bsrc_row + bc4, bpred);
        CP_COMMIT();
    }

    for (int kc = 0; kc < nk; kc++) {
        int cur = kc & 1;
        if (kc + 1 < nk) {
            int k0 = (kc + 1) << 4;
            uint32_t so = (uint32_t)((kc + 1) & 1);
            cp16(aBase + so*A_STAGE + (uint32_t)((ar0*TSTR + ac4)*4),
                 A + (size_t)(bm + ar0)*lda + k0 + ac4, 16);
            cp16(aBase + so*A_STAGE + (uint32_t)(((ar0+64)*TSTR + ac4)*4),
                 A + (size_t)(bm + ar0 + 64)*lda + k0 + ac4, 16);
            cp16(bBase + so*B_STAGE + (uint32_t)((br*TSTR + bc4)*4),
                 bsrc_row + k0 + bc4, bpred);
            CP_COMMIT();
            CP_WAIT(1);
        } else {
            CP_WAIT(0);
        }
        __syncthreads();

        const float* cA = sA[cur];
        const float* cB = sB[cur];

        #pragma unroll
        for (int ks = 0; ks < 2; ks++) {
            int kk = ks * 8;
            uint32_t ah[2][4], al[2][4];
            {
                int r0 = warp_m*32 + (lid >> 2);
                int c0 = kk + (lid & 3);
                #pragma unroll
                for (int im = 0; im < 2; im++) {
                    const float* pa = cA + (r0 + im*16)*TSTR + c0;
                    float f0 = pa[0], f1 = pa[8*TSTR], f2 = pa[4], f3 = pa[8*TSTR + 4];
                    ah[im][0] = f2tf32(f0); al[im][0] = f2tf32(f0 - __uint_as_float(ah[im][0]));
                    ah[im][1] = f2tf32(f1); al[im][1] = f2tf32(f1 - __uint_as_float(ah[im][1]));
                    ah[im][2] = f2tf32(f2); al[im][2] = f2tf32(f2 - __uint_as_float(ah[im][2]));
                    ah[im][3] = f2tf32(f3); al[im][3] = f2tf32(f3 - __uint_as_float(ah[im][3]));
                }
            }
            uint32_t bh[4][2], bl[4][2];
            {
                int n0 = warp_n*32 + (lid >> 2);
                int c0 = kk + (lid & 3);
                #pragma unroll
                for (int jn = 0; jn < 4; jn++) {
                    const float* pb = cB + (n0 + jn*8)*TSTR + c0;
                    float f0 = pb[0], f1 = pb[4];
                    bh[jn][0] = f2tf32(f0); bl[jn][0] = f2tf32(f0 - __uint_as_float(bh[jn][0]));
                    bh[jn][1] = f2tf32(f1); bl[jn][1] = f2tf32(f1 - __uint_as_float(bh[jn][1]));
                }
            }
            #pragma unroll
            for (int im = 0; im < 2; im++)
                #pragma unroll
                for (int jn = 0; jn < 4; jn++) {
                    mma16n8k8(acc[im][jn], ah[im], bh[jn]);
                    mma16n8k8(acc[im][jn], al[im], bh[jn]);
                    mma16n8k8(acc[im][jn], ah[im], bl[jn]);
                }
        }
        __syncthreads();
    }

    // ---- epilogue ----
    int gm0 = bm + warp_m*32 + (lid >> 2);
    int gnb = bn + warp_n*32 + 2*(lid & 3);
    #pragma unroll
    for (int im = 0; im < 2; im++) {
        #pragma unroll
        for (int jn = 0; jn < 4; jn++) {
            int gn = gnb + jn*8;
            if (gn < N) {
                float b0 = 0.f, b1 = 0.f;
                if (bias) { b0 = bias[gn]; b1 = bias[gn+1]; }
                #pragma unroll
                for (int half = 0; half < 2; half++) {
                    int gm = gm0 + im*16 + half*8;
                    float v0 = acc[im][jn][half*2+0] + b0;
                    float v1 = acc[im][jn][half*2+1] + b1;
                    if (act == 1) {   // softplus
                        v0 = (v0 > 15.f) ? v0 : log1pf(__expf(v0));
                        v1 = (v1 > 15.f) ? v1 : log1pf(__expf(v1));
                    }
                    if (res) {
                        float2 rv = *(const float2*)(res + (size_t)gm*N + gn);
                        v0 += rv.x; v1 += rv.y;
                    }
                    *(float2*)(C + (size_t)gm*N + gn) = make_float2(v0, v1);
                }
            }
        }
    }
}

// ---------------- depthwise causal conv (width 4) + SiLU --------------------
__global__ void conv_silu_kernel(const float* __restrict__ xz,
                                 const float* __restrict__ convw,
                                 const float* __restrict__ convb,
                                 float* __restrict__ u)
{
    int idx = blockIdx.x * blockDim.x + threadIdx.x;
    if (idx >= BL*DI) return;
    int d  = idx & (DI-1);
    int bt = idx >> 9;
    int t  = bt & (LL-1);

    float acc = convb[d];
    #pragma unroll
    for (int k = 0; k < DCONV; k++) {
        int tt = t - (DCONV-1) + k;
        if (tt >= 0)
            acc = fmaf(xz[(size_t)(bt - (DCONV-1) + k)*(2*DI) + d],
                       convw[d*DCONV + k], acc);
    }
    float sig = 1.f / (1.f + __expf(-acc));
    u[idx] = acc * sig;
}

// ============ chunked selective scan: block per (b,d), 16 chunks =============
// thread = (chunk 0..15) x (state 0..15). Pass1: local scan from 0 + sum(delta).
// Chunk transition P = exp(A * sum(delta)) (exact product of dA's).
// smem prefix over chunks gives true h_start; pass2 rescans and emits y.
__global__ __launch_bounds__(256) void scan2_kernel(
    const float* __restrict__ xz,
    const float* __restrict__ u_arr,
    const float* __restrict__ dbc,
    const float* __restrict__ delta_arr,
    const float* __restrict__ a_log,
    const float* __restrict__ dparam,
    float* __restrict__ y_arr)
{
    __shared__ float s_delta[LL];    // 8KB
    __shared__ float s_u[LL];        // 8KB
    __shared__ float sC[16][17];
    __shared__ float sP[16][17];

    int bd = blockIdx.x;             // 0..2047
    int d = bd & (DI-1), b = bd >> 9;
    int tid = threadIdx.x;
    int s = tid & 15, ck = tid >> 4;
    int t0 = ck * 128;
    int base = b * LL;

    float A = -__expf(a_log[d*DS + s]);

    // ---- pass 1: chunk-local scan from h=0 ----
    float hloc = 0.f, sd = 0.f;
    #pragma unroll 4
    for (int i = 0; i < 128; i++) {
        int t = t0 + i;
        int row = base + t;
        float delta = delta_arr[(size_t)row*DI + d];
        float uu    = u_arr[(size_t)row*DI + d];
        float Bt    = dbc[(size_t)row*48 + DTR + s];
        float dA = __expf(delta * A);
        hloc = fmaf(dA, hloc, delta * uu * Bt);
        sd += delta;
        if (s == 0) { s_delta[t] = delta; s_u[t] = uu; }
    }
    sC[ck][s] = hloc;
    sP[ck][s] = __expf(sd * A);
    __syncthreads();

    // ---- prefix over chunks (16 threads, one per state) ----
    if (tid < 16) {
        float h = 0.f;
        #pragma unroll
        for (int c = 0; c < 16; c++) {
            float nh = fmaf(sP[c][tid], h, sC[c][tid]);
            sC[c][tid] = h;       // h_start for chunk c
            h = nh;
        }
    }
    __syncthreads();

    // ---- pass 2: rescan with true h_start, emit y ----
    float h = sC[ck][s];
    float Dp = dparam[d];
    #pragma unroll 4
    for (int i = 0; i < 128; i++) {
        int t = t0 + i;
        int row = base + t;
        float delta = s_delta[t];
        float uu    = s_u[t];
        float Bt    = dbc[(size_t)row*48 + DTR + s];
        float Ct    = dbc[(size_t)row*48 + DTR + DS + s];
        float dA = __expf(delta * A);
        h = fmaf(dA, h, delta * uu * Bt);

        float p = h * Ct;
        p += __shfl_xor_sync(0xffffffffu, p, 8);
        p += __shfl_xor_sync(0xffffffffu, p, 4);
        p += __shfl_xor_sync(0xffffffffu, p, 2);
        p += __shfl_xor_sync(0xffffffffu, p, 1);

        if (s == 0) {
            float z = xz[(size_t)row*(2*DI) + DI + d];
            float sig = 1.f / (1.f + __expf(-z));
            y_arr[(size_t)row*DI + d] = (p + uu * Dp) * (z * sig);
        }
    }
}

// ---------------- layernorm over 256 features (one warp per row) ------------
__global__ void ln_kernel(const float* __restrict__ x,
                          const float* __restrict__ w,
                          const float* __restrict__ b,
                          float* __restrict__ out)
{
    int warp = (blockIdx.x * blockDim.x + threadIdx.x) >> 5;
    int lane = threadIdx.x & 31;
    if (warp >= BL) return;
    const float* row = x + (size_t)warp*DM;

    float v[8];
    float sum = 0.f, sq = 0.f;
    #pragma unroll
    for (int k = 0; k < 8; k++) {
        v[k] = row[lane + k*32];
        sum += v[k];
        sq = fmaf(v[k], v[k], sq);
    }
    #pragma unroll
    for (int o = 16; o; o >>= 1) {
        sum += __shfl_xor_sync(0xffffffffu, sum, o);
        sq  += __shfl_xor_sync(0xffffffffu, sq,  o);
    }
    float mu  = sum * (1.f/DM);
    float var = sq * (1.f/DM) - mu*mu;
    float inv = rsqrtf(var + 1e-5f);
    #pragma unroll
    for (int k = 0; k < 8; k++) {
        int c = lane + k*32;
        out[(size_t)warp*DM + c] = (v[k]-mu)*inv*w[c] + b[c];
    }
}

// ---------------- host orchestration ----------------------------------------
static inline void launch_gemm(const float* A, int lda, const float* W,
                               const float* bias, const float* res,
                               float* C, int N, int K, int act)
{
    dim3 grid((N + 63) / 64, BL / 128);
    mma_gemm<<<grid, 256>>>(A, lda, W, bias, res, C, N, K, act);
}

extern "C" void kernel_launch(void* const* d_in, const int* in_sizes, int n_in,
                              void* d_out, int out_size)
{
    const float* x          = (const float*)d_in[0];
    const float* in_proj_w  = (const float*)d_in[1];
    const float* in_proj_b  = (const float*)d_in[2];
    const float* out_proj_w = (const float*)d_in[3];
    const float* out_proj_b = (const float*)d_in[4];
    const float* inw        = (const float*)d_in[5];
    const float* convw      = (const float*)d_in[6];
    const float* convb      = (const float*)d_in[7];
    const float* xpw        = (const float*)d_in[8];
    const float* dtw        = (const float*)d_in[9];
    const float* dtb        = (const float*)d_in[10];
    const float* a_log      = (const float*)d_in[11];
    const float* dparam     = (const float*)d_in[12];
    const float* outw       = (const float*)d_in[13];
    const float* lnw        = (const float*)d_in[14];
    const float* lnb        = (const float*)d_in[15];
    float* out = (float*)d_out;

    float *h, *xz, *u, *dbc, *delta, *y, *ln;
    cudaGetSymbolAddress((void**)&h,     g_h);
    cudaGetSymbolAddress((void**)&xz,    g_xz);
    cudaGetSymbolAddress((void**)&u,     g_u);
    cudaGetSymbolAddress((void**)&dbc,   g_dbc);
    cudaGetSymbolAddress((void**)&delta, g_delta);
    cudaGetSymbolAddress((void**)&y,     g_y);
    cudaGetSymbolAddress((void**)&ln,    g_ln);

    // h = x @ in_proj_w^T + in_proj_b
    launch_gemm(x, IN_DIM, in_proj_w, in_proj_b, nullptr, h, DM, IN_DIM, 0);

    for (int l = 0; l < NLAYERS; l++) {
        // xz = h @ inw[l]^T
        launch_gemm(h, DM, inw + (size_t)l*2*DI*DM, nullptr, nullptr, xz, 2*DI, DM, 0);
        // u = silu(causal_conv(xz[:, :DI]))
        conv_silu_kernel<<<(BL*DI)/256, 256>>>(xz, convw + l*DI*DCONV, convb + l*DI, u);
        // dbc = u @ xpw[l]^T   (N=48 with guards)
        launch_gemm(u, DI, xpw + (size_t)l*48*DI, nullptr, nullptr, dbc, 48, DI, 0);
        // delta = softplus(dt @ dtw[l]^T + dtb[l])
        launch_gemm(dbc, 48, dtw + (size_t)l*DI*DTR, dtb + l*DI, nullptr, delta, DI, DTR, 1);
        // chunked selective scan + gating
        scan2_kernel<<<BB*DI, 256>>>(xz, u, dbc, delta,
                                     a_log + (size_t)l*DI*DS, dparam + l*DI, y);
        // ln_in = y @ outw[l]^T + residual(h)
        launch_gemm(y, DI, outw + (size_t)l*DM*DI, nullptr, h, ln, DM, DI, 0);
        // h = layernorm(ln_in)
        ln_kernel<<<BL/8, 256>>>(ln, lnw + l*DM, lnb + l*DM, h);
    }

    // out = h @ out_proj_w^T + out_proj_b
    launch_gemm(h, DM, out_proj_w, out_proj_b, nullptr, out, DM, DM, 0);
}